// round 13
// baseline (speedup 1.0000x reference)
#include <cuda_runtime.h>
#include <cuda_bf16.h>

#define NN 10
#define DD 64
#define MS 72

__device__ float g_M9[DD][DD];            // out = x @ g_M9 + g_dv9
__device__ float g_dv9[DD];
__device__ volatile unsigned g_flag;      // precompute-done counter (0..33)
__device__ unsigned g_done;               // gemm-block completion counter

__device__ __forceinline__ unsigned tf32_rna(float v) {
    unsigned u = __float_as_uint(v);
    return (u + 0x1000u) & 0xFFFFE000u;
}

__device__ __forceinline__ void mma_tf32(float& c0, float& c1, float& c2, float& c3,
                                         unsigned a0, unsigned a1, unsigned a2, unsigned a3,
                                         unsigned b0, unsigned b1) {
    asm volatile(
        "mma.sync.aligned.m16n8k8.row.col.f32.tf32.tf32.f32 "
        "{%0,%1,%2,%3}, {%4,%5,%6,%7}, {%8,%9}, {%0,%1,%2,%3};"
        : "+f"(c0), "+f"(c1), "+f"(c2), "+f"(c3)
        : "r"(a0), "r"(a1), "r"(a2), "r"(a3), "r"(b0), "r"(b1));
}

// ---- precompute role: blocks 0..32 (R8 body; partner SMs kept quiet) --------
__device__ void precompute_role(const float* __restrict__ W,
                                const float* __restrict__ B,
                                float* sh, int bi) {
    float* rowsh = sh;                    // [NN][2][DD]
    float* red   = sh + NN * 2 * DD;      // [16][2][DD]
    const int tid  = threadIdx.x;
    const bool bias = (bi == 32);
    const int d0   = bi * 2;
    const int kk   = tid >> 4;
    const int hg   = tid & 15;
    const int rr   = tid >> 6;
    const int hh   = tid & 63;

    if (tid < 128)
        rowsh[(0 * 2 + rr) * DD + hh] = (!bias && (d0 + rr == hh)) ? 1.f : 0.f;
    __syncthreads();

    #pragma unroll
    for (int t = 1; t <= 9; ++t) {
        float extra = 0.f;
        if (tid < 128) {
            if (!bias) {
                extra = W[((size_t)t * DD + (d0 + rr)) * DD + hh];
            } else if (rr == 0) {
                #pragma unroll
                for (int f = 0; f < t; ++f)
                    extra += B[((size_t)f * NN + t) * DD + hh];
            }
        }

        float4 a0 = make_float4(0.f, 0.f, 0.f, 0.f);
        float4 a1 = make_float4(0.f, 0.f, 0.f, 0.f);

        #pragma unroll
        for (int f = 1; f < t; ++f) {
            const float* Wb = W + (((size_t)f * NN + t) * DD + kk * 4) * DD + hg * 4;
            float4 w0 = *reinterpret_cast<const float4*>(Wb + 0 * DD);
            float4 w1 = *reinterpret_cast<const float4*>(Wb + 1 * DD);
            float4 w2 = *reinterpret_cast<const float4*>(Wb + 2 * DD);
            float4 w3 = *reinterpret_cast<const float4*>(Wb + 3 * DD);
            float4 r0 = *reinterpret_cast<const float4*>(&rowsh[(f * 2 + 0) * DD + kk * 4]);
            float4 r1 = *reinterpret_cast<const float4*>(&rowsh[(f * 2 + 1) * DD + kk * 4]);
            a0.x += r0.x * w0.x + r0.y * w1.x + r0.z * w2.x + r0.w * w3.x;
            a0.y += r0.x * w0.y + r0.y * w1.y + r0.z * w2.y + r0.w * w3.y;
            a0.z += r0.x * w0.z + r0.y * w1.z + r0.z * w2.z + r0.w * w3.z;
            a0.w += r0.x * w0.w + r0.y * w1.w + r0.z * w2.w + r0.w * w3.w;
            a1.x += r1.x * w0.x + r1.y * w1.x + r1.z * w2.x + r1.w * w3.x;
            a1.y += r1.x * w0.y + r1.y * w1.y + r1.z * w2.y + r1.w * w3.y;
            a1.z += r1.x * w0.z + r1.y * w1.z + r1.z * w2.z + r1.w * w3.z;
            a1.w += r1.x * w0.w + r1.y * w1.w + r1.z * w2.w + r1.w * w3.w;
        }
        *reinterpret_cast<float4*>(&red[(kk * 2 + 0) * DD + hg * 4]) = a0;
        *reinterpret_cast<float4*>(&red[(kk * 2 + 1) * DD + hg * 4]) = a1;
        __syncthreads();

        if (tid < 128) {
            float s = extra;
            #pragma unroll
            for (int k2 = 0; k2 < 16; ++k2) s += red[(k2 * 2 + rr) * DD + hh];
            rowsh[(t * 2 + rr) * DD + hh] = s;
            if (t == 9) {
                if (!bias)        g_M9[d0 + rr][hh] = s;
                else if (rr == 0) g_dv9[hh] = s;
            }
        }
        __syncthreads();
    }

    __threadfence();
    __syncthreads();
    if (tid == 0) atomicAdd((unsigned*)&g_flag, 1u);
}

// ---- gemm role: 256 logical blocks, 256 rows each ---------------------------
// deferred=true for the 26 blocks sharing SMs with precompute: they issue NO
// memory traffic before the flag (keeps the precompute SMs' L1tex queue clean).
__device__ void gemm_role(const float* __restrict__ x, float* __restrict__ out,
                          unsigned* shb, int bid, bool deferred) {
    unsigned* Msm = shb;                                  // [64][MS]
    unsigned* xs2 = shb + 64 * MS;                        // [128][MS] tf32 half-2 rows
    float*    dvs = reinterpret_cast<float*>(xs2 + 128 * MS);
    const int tid  = threadIdx.x;
    const int w    = tid >> 5;
    const int lane = tid & 31;
    const int g    = lane >> 2;
    const int t    = lane & 3;
    const int R0   = bid * 256;
    const int rowA = R0 + w * 16 + g;                     // half-1 rows: rowA, rowA+8

    unsigned af1[8][4];

    if (!deferred) {
        // ---- pre-wake 1: half-1 A fragments into registers ----
        const float2* a0p = reinterpret_cast<const float2*>(x + (size_t)rowA * DD);
        const float2* a1p = reinterpret_cast<const float2*>(x + (size_t)(rowA + 8) * DD);
        #pragma unroll
        for (int k8 = 0; k8 < 8; ++k8) {
            float2 v0 = a0p[4 * k8 + t];
            float2 v1 = a1p[4 * k8 + t];
            af1[k8][0] = tf32_rna(v0.x); af1[k8][2] = tf32_rna(v0.y);
            af1[k8][1] = tf32_rna(v1.x); af1[k8][3] = tf32_rna(v1.y);
        }
        // ---- pre-wake 2: half-2 rows tf32-staged into shared ----
        const int r    = tid >> 1;
        const int half = tid & 1;
        const float4* src = reinterpret_cast<const float4*>(
            x + (size_t)(R0 + 128 + r) * DD + half * 32);
        #pragma unroll
        for (int i = 0; i < 8; ++i) {
            float4 v = src[i];
            uint4 u = make_uint4(tf32_rna(v.x), tf32_rna(v.y), tf32_rna(v.z), tf32_rna(v.w));
            *reinterpret_cast<uint4*>(&xs2[r * MS + half * 32 + 4 * i]) = u;
        }
    }

    // ---- wait: single-thread spin, rest park at the barrier ----
    if (tid == 0) {
        while (g_flag < 33u) __nanosleep(64);
        __threadfence();
    }
    __syncthreads();

    if (deferred) {
        // post-wake staging (identical work, after the chain is done)
        const float2* a0p = reinterpret_cast<const float2*>(x + (size_t)rowA * DD);
        const float2* a1p = reinterpret_cast<const float2*>(x + (size_t)(rowA + 8) * DD);
        #pragma unroll
        for (int k8 = 0; k8 < 8; ++k8) {
            float2 v0 = a0p[4 * k8 + t];
            float2 v1 = a1p[4 * k8 + t];
            af1[k8][0] = tf32_rna(v0.x); af1[k8][2] = tf32_rna(v0.y);
            af1[k8][1] = tf32_rna(v1.x); af1[k8][3] = tf32_rna(v1.y);
        }
        const int r    = tid >> 1;
        const int half = tid & 1;
        const float4* src = reinterpret_cast<const float4*>(
            x + (size_t)(R0 + 128 + r) * DD + half * 32);
        #pragma unroll
        for (int i = 0; i < 8; ++i) {
            float4 v = src[i];
            uint4 u = make_uint4(tf32_rna(v.x), tf32_rna(v.y), tf32_rna(v.z), tf32_rna(v.w));
            *reinterpret_cast<uint4*>(&xs2[r * MS + half * 32 + 4 * i]) = u;
        }
    }

    // ---- stage M^T + bias ----
    {
        const float* Mflat = &g_M9[0][0];
        #pragma unroll
        for (int i = 0; i < 16; ++i) {
            int idx = i * 256 + tid;
            int k = idx >> 6, n = idx & 63;
            Msm[n * MS + k] = tf32_rna(Mflat[idx]);
        }
        if (tid < 64) dvs[tid] = g_dv9[tid];
    }
    __syncthreads();

    float2 dvp[8];
    #pragma unroll
    for (int n = 0; n < 8; ++n)
        dvp[n] = *reinterpret_cast<const float2*>(&dvs[8 * n + 2 * t]);

    // ---- half 1: A from registers ----
    {
        float acc[8][4];
        #pragma unroll
        for (int n = 0; n < 8; ++n)
            #pragma unroll
            for (int c = 0; c < 4; ++c) acc[n][c] = 0.f;
        #pragma unroll
        for (int k8 = 0; k8 < 8; ++k8) {
            const int kcol = 8 * k8 + 2 * t;
            #pragma unroll
            for (int n = 0; n < 8; ++n) {
                uint2 bf = *reinterpret_cast<const uint2*>(&Msm[(8 * n + g) * MS + kcol]);
                mma_tf32(acc[n][0], acc[n][1], acc[n][2], acc[n][3],
                         af1[k8][0], af1[k8][1], af1[k8][2], af1[k8][3], bf.x, bf.y);
            }
        }
        #pragma unroll
        for (int n = 0; n < 8; ++n) {
            float2 o0 = make_float2(acc[n][0] + dvp[n].x, acc[n][1] + dvp[n].y);
            float2 o1 = make_float2(acc[n][2] + dvp[n].x, acc[n][3] + dvp[n].y);
            *reinterpret_cast<float2*>(out + (size_t)rowA * DD + 8 * n + 2 * t)       = o0;
            *reinterpret_cast<float2*>(out + (size_t)(rowA + 8) * DD + 8 * n + 2 * t) = o1;
        }
    }
    // ---- half 2: A fragments from shared (conflict-free LDS.64) ----
    {
        const int lr = w * 16 + g;
        float acc[8][4];
        #pragma unroll
        for (int n = 0; n < 8; ++n)
            #pragma unroll
            for (int c = 0; c < 4; ++c) acc[n][c] = 0.f;
        #pragma unroll
        for (int k8 = 0; k8 < 8; ++k8) {
            const int kcol = 8 * k8 + 2 * t;
            uint2 a0 = *reinterpret_cast<const uint2*>(&xs2[lr * MS + kcol]);
            uint2 a1 = *reinterpret_cast<const uint2*>(&xs2[(lr + 8) * MS + kcol]);
            #pragma unroll
            for (int n = 0; n < 8; ++n) {
                uint2 bf = *reinterpret_cast<const uint2*>(&Msm[(8 * n + g) * MS + kcol]);
                mma_tf32(acc[n][0], acc[n][1], acc[n][2], acc[n][3],
                         a0.x, a1.x, a0.y, a1.y, bf.x, bf.y);
            }
        }
        const int rowB = R0 + 128 + lr;
        #pragma unroll
        for (int n = 0; n < 8; ++n) {
            float2 o0 = make_float2(acc[n][0] + dvp[n].x, acc[n][1] + dvp[n].y);
            float2 o1 = make_float2(acc[n][2] + dvp[n].x, acc[n][3] + dvp[n].y);
            *reinterpret_cast<float2*>(out + (size_t)rowB * DD + 8 * n + 2 * t)       = o0;
            *reinterpret_cast<float2*>(out + (size_t)(rowB + 8) * DD + 8 * n + 2 * t) = o1;
        }
    }

    // ---- replay hygiene: last gemm block resets the counters ----
    __syncthreads();
    if (tid == 0) {
        unsigned v = atomicAdd(&g_done, 1u);
        if (v == 255u) {
            g_done = 0u;
            g_flag = 0u;
            __threadfence();
        }
    }
}

// Grid = 296 = exactly one wave at 2 CTA/SM: blocks b and b+148 share an SM.
// bids 0..32: precompute. bids 148..154: idle (partners of 7 precompute SMs).
// bids 155..180: deferred gemm (partners of the other 26 precompute SMs).
// Everything else: normal gemm with pre-wake x prefetch.
__global__ __launch_bounds__(256, 2) void fused_kernel(const float* __restrict__ x,
                                                       const float* __restrict__ W,
                                                       const float* __restrict__ B,
                                                       float* __restrict__ out) {
    extern __shared__ __align__(16) float sh[];
    const int bid = blockIdx.x;
    if (bid < 33) {
        precompute_role(W, B, sh, bid);
        return;
    }
    if (bid >= 148 && bid < 155) return;                  // idle partners
    int idx;
    bool deferred = false;
    if (bid >= 155 && bid < 181) { idx = 230 + (bid - 155); deferred = true; }
    else if (bid < 148)          { idx = bid - 33; }
    else                         { idx = 115 + (bid - 181); }
    gemm_role(x, out, reinterpret_cast<unsigned*>(sh), idx, deferred);
}

extern "C" void kernel_launch(void* const* d_in, const int* in_sizes, int n_in,
                              void* d_out, int out_size) {
    const float* x = (const float*)d_in[0];
    const float* W = (const float*)d_in[1];
    const float* b = (const float*)d_in[2];
    float* out = (float*)d_out;

    const int smem_bytes = (64 * MS + 128 * MS + 64) * 4;   // 55552
    cudaFuncSetAttribute(fused_kernel, cudaFuncAttributeMaxDynamicSharedMemorySize, smem_bytes);

    fused_kernel<<<296, 256, smem_bytes>>>(x, W, b, out);
}